// round 15
// baseline (speedup 1.0000x reference)
#include <cuda_runtime.h>
#include <cuda_bf16.h>
#include <cuda_fp16.h>
#include <cstdint>

// Problem constants
#define NROWS   8192
#define DIN     1024
#define DHID    16384
#define TOPK    32
#define BANDCAP 64
#define CAP     1024          // candidate buffer per row
#define TAU     0.78f         // static candidate threshold (~2.3 sigma)
#define BANDM   1e-3f         // refinement band half-width

// Output layout:
//   x_hat    [8192,1024]   @ 0
//   z_sparse [8192,16384]  @ 8388608
//   z        [8192,16384]  @ 142606336
//   active   scalar        @ 276824064
#define OFF_XHAT   0
#define OFF_ZSP    8388608
#define OFF_Z      142606336
#define OFF_ACT    276824064

// -------- device scratch (no allocations allowed) --------
__device__ __half g_WdecT[(size_t)DHID * DIN];                               // 32 MB fp16
__device__ __align__(256) unsigned char g_xh[(size_t)NROWS * DIN * 2];       // fp16 x
__device__ __align__(256) unsigned char g_wh[(size_t)DHID * DIN * 2];        // fp16 W_enc
__device__ uint2 g_cand[(size_t)NROWS * CAP];                                // 64 MB (valbits, idx)
__device__ int   g_cand_cnt[NROWS];
__device__ int   g_pos;
__device__ int   g_done;

// ---------------- PTX helpers (baseline compute_103 feature set only) -------
__device__ __forceinline__ uint32_t smem_u32(const void* p) {
    uint32_t a;
    asm("{ .reg .u64 t; cvta.to.shared.u64 t, %1; cvt.u32.u64 %0, t; }" : "=r"(a) : "l"(p));
    return a;
}
__device__ __forceinline__ void cp16(uint32_t dst, const void* src) {
    asm volatile("cp.async.cg.shared.global [%0], [%1], 16;" :: "r"(dst), "l"(src));
}
#define CP_COMMIT() asm volatile("cp.async.commit_group;" ::: "memory")
#define CP_WAIT1()  asm volatile("cp.async.wait_group 1;" ::: "memory")

__device__ __forceinline__ void ldm4(uint32_t* d, uint32_t addr) {
    asm volatile("ldmatrix.sync.aligned.m8n8.x4.shared.b16 {%0,%1,%2,%3}, [%4];"
        : "=r"(d[0]), "=r"(d[1]), "=r"(d[2]), "=r"(d[3]) : "r"(addr));
}
__device__ __forceinline__ void mma_f16(float* c, const uint32_t* a, const uint32_t* b) {
    asm volatile("mma.sync.aligned.m16n8k16.row.col.f32.f16.f16.f32 "
        "{%0,%1,%2,%3}, {%4,%5,%6,%7}, {%8,%9}, {%0,%1,%2,%3};"
        : "+f"(c[0]), "+f"(c[1]), "+f"(c[2]), "+f"(c[3])
        : "r"(a[0]), "r"(a[1]), "r"(a[2]), "r"(a[3]), "r"(b[0]), "r"(b[1]));
}

// conflict-free chunk swizzle for 256B rows (16 x 16B chunks):
// XOR of the low 3 chunk bits — any 8 consecutive rows at one c16 hit 8
// distinct chunks => all 32 banks; cp.async 16-thread groups stay contiguous.
__device__ __forceinline__ uint32_t swz(int r, int c16) {
    return (uint32_t)(r * 256 + ((c16 ^ (r & 7)) << 4));
}

// ---------------- prep: pack W_enc + pack x + reset --------------------------
// block ranges:
//   [0, 8192)        pack W_enc -> fp16      (2048 elems each)
//   [8192, 12288)    pack x -> fp16          (4096 blocks)
//   [12288, 12320)   reset counters          (32 blocks)
__global__ void prep_kernel(const float* __restrict__ x,
                            const float* __restrict__ Wenc,
                            uint4* __restrict__ xh, uint4* __restrict__ wh) {
    const int b = blockIdx.x, t = threadIdx.x;
    if (b < 12288) {
        const bool isW = (b < 8192);
        const int i = (isW ? b : (b - 8192)) * 256 + t;
        const float4* src = (const float4*)(isW ? Wenc : x);
        uint4* dst = isW ? wh : xh;
        float4 a = src[2 * i], c = src[2 * i + 1];
        __half2 h0 = __floats2half2_rn(a.x, a.y);
        __half2 h1 = __floats2half2_rn(a.z, a.w);
        __half2 h2 = __floats2half2_rn(c.x, c.y);
        __half2 h3 = __floats2half2_rn(c.z, c.w);
        uint4 o;
        o.x = *reinterpret_cast<unsigned*>(&h0);
        o.y = *reinterpret_cast<unsigned*>(&h1);
        o.z = *reinterpret_cast<unsigned*>(&h2);
        o.w = *reinterpret_cast<unsigned*>(&h3);
        dst[i] = o;
    } else {
        const int i = (b - 12288) * 256 + t;
        if (i < NROWS) g_cand_cnt[i] = 0;
        if (i == 0) { g_pos = 0; g_done = 0; }
    }
}

// ---------------- encoder: fp16 HMMA GEMM + relu + z_sp zeros + candidates --
// KTILE=128: 8 barrier rounds (was 16). 192 KB smem, occupancy 1.
// Prologue: each CTA transposes 2 W_dec 32x32 tiles into fp16 WdecT (scratch
// in not-yet-live stage smem); completion before select is implied by order.
#define KTILE   128
#define STAGES  3
#define TILE_B  32768
#define STAGE_B 65536
#define GEMM_SMEM (STAGES * STAGE_B)

__global__ __launch_bounds__(256, 1)
void mma_gemm_kernel(const unsigned char* __restrict__ Ah,
                     const unsigned char* __restrict__ Bh,
                     const float* __restrict__ Wdec,
                     __half* __restrict__ WdecT,
                     float* __restrict__ z, float* __restrict__ z_sp) {
    extern __shared__ unsigned char smem[];
    const uint32_t sb = smem_u32(smem);
    const int tid = threadIdx.x;
    const int lane = tid & 31, warp = tid >> 5;
    const int wm = warp & 3, wn = warp >> 2;
    const int m0 = blockIdx.y * 128, n0 = blockIdx.x * 128;

    // ---- prologue: transpose 2 W_dec tiles using stage smem as scratch ----
    {
        float (*tile)[33] = reinterpret_cast<float (*)[33]>(smem);
        const int L = blockIdx.y * gridDim.x + blockIdx.x;   // 0..8191
        const int tx = tid & 31, ty = tid >> 5;              // (32, 8)
#pragma unroll
        for (int q = 0; q < 2; q++) {
            const int tt = 2 * L + q;
            const int h0 = (tt & 511) * 32;
            const int d0 = (tt >> 9) * 32;
#pragma unroll
            for (int j = 0; j < 32; j += 8)
                tile[ty + j][tx] = Wdec[(size_t)(d0 + ty + j) * DHID + h0 + tx];
            __syncthreads();
#pragma unroll
            for (int j = 0; j < 32; j += 8)
                WdecT[(size_t)(h0 + ty + j) * DIN + d0 + tx] = __float2half(tile[tx][ty + j]);
            __syncthreads();
        }
    }

    float acc[2][8][4];
#pragma unroll
    for (int i = 0; i < 2; i++)
#pragma unroll
        for (int j = 0; j < 8; j++)
#pragma unroll
            for (int q = 0; q < 4; q++) acc[i][j][q] = 0.f;

    // stage loader: 2 subtiles x 2048 16B-chunks, 16 cp.async per thread
    auto load_stage = [&](int s, int kc) {
        const uint32_t stage = sb + s * STAGE_B;
#pragma unroll
        for (int t = 0; t < 2; t++) {
            const int r0 = t ? n0 : m0;
            const unsigned char* g = t ? Bh : Ah;
#pragma unroll
            for (int rep = 0; rep < 8; rep++) {
                const int j = tid + rep * 256;
                const int r = j >> 4, c16 = j & 15;
                const unsigned char* src = g + (((size_t)(r0 + r) << 10) + kc * 128 + c16 * 8) * 2;
                cp16(stage + t * TILE_B + swz(r, c16), src);
            }
        }
    };

    load_stage(0, 0); CP_COMMIT();
    load_stage(1, 1); CP_COMMIT();

    for (int kc = 0; kc < DIN / KTILE; kc++) {      // 8 iterations
        CP_WAIT1();                      // stage kc's data complete
        __syncthreads();                 // all threads done reading stage kc-1
        if (kc + 2 < DIN / KTILE) load_stage((kc + 2) % STAGES, kc + 2);
        CP_COMMIT();
        const uint32_t stage = sb + (kc % STAGES) * STAGE_B;

#pragma unroll
        for (int ks = 0; ks < 8; ks++) {
            uint32_t ah[2][4], bh[8][2];
#pragma unroll
            for (int i = 0; i < 2; i++) {
                const int row = wm * 32 + i * 16 + (lane & 15);
                const int c16 = ks * 2 + (lane >> 4);
                ldm4(ah[i], stage + swz(row, c16));
            }
#pragma unroll
            for (int g = 0; g < 4; g++) {
                const int row = wn * 64 + g * 16 + (lane & 7) + ((lane >> 4) << 3);
                const int c16 = ks * 2 + ((lane >> 3) & 1);
                uint32_t d[4];
                ldm4(d, stage + TILE_B + swz(row, c16));
                bh[2 * g][0] = d[0]; bh[2 * g][1] = d[1];
                bh[2 * g + 1][0] = d[2]; bh[2 * g + 1][1] = d[3];
            }
#pragma unroll
            for (int i = 0; i < 2; i++)
#pragma unroll
                for (int j = 0; j < 8; j++)
                    mma_f16(acc[i][j], ah[i], bh[j]);
        }
    }

    // epilogue: relu + z store + z_sp zero store + candidate push (v > TAU)
    const int mbase = m0 + wm * 32, nbase = n0 + wn * 64;
    const float2 zero2 = make_float2(0.f, 0.f);
#pragma unroll
    for (int i = 0; i < 2; i++)
#pragma unroll
        for (int j = 0; j < 8; j++) {
            const int r = mbase + i * 16 + (lane >> 2);
            const int c = nbase + j * 8 + (lane & 3) * 2;
            float2 v0, v1;
            v0.x = fmaxf(acc[i][j][0], 0.f); v0.y = fmaxf(acc[i][j][1], 0.f);
            v1.x = fmaxf(acc[i][j][2], 0.f); v1.y = fmaxf(acc[i][j][3], 0.f);
            *(float2*)(z + (size_t)r * DHID + c) = v0;
            *(float2*)(z + (size_t)(r + 8) * DHID + c) = v1;
            *(float2*)(z_sp + (size_t)r * DHID + c) = zero2;
            *(float2*)(z_sp + (size_t)(r + 8) * DHID + c) = zero2;
            if (v0.x > TAU) { int s = atomicAdd(&g_cand_cnt[r], 1);
                if (s < CAP) g_cand[(size_t)r * CAP + s] = make_uint2(__float_as_uint(v0.x), c); }
            if (v0.y > TAU) { int s = atomicAdd(&g_cand_cnt[r], 1);
                if (s < CAP) g_cand[(size_t)r * CAP + s] = make_uint2(__float_as_uint(v0.y), c + 1); }
            if (v1.x > TAU) { int s = atomicAdd(&g_cand_cnt[r + 8], 1);
                if (s < CAP) g_cand[(size_t)(r + 8) * CAP + s] = make_uint2(__float_as_uint(v1.x), c); }
            if (v1.y > TAU) { int s = atomicAdd(&g_cand_cnt[r + 8], 1);
                if (s < CAP) g_cand[(size_t)(r + 8) * CAP + s] = make_uint2(__float_as_uint(v1.y), c + 1); }
        }
}

// ---------------- merged: top-k + fallback + fp64 refine + decoder + active -
// One block (256 threads) per row; the last block to finish writes `active`.
__global__ void select_kernel(const float* __restrict__ z,
                              const float* __restrict__ x,
                              const float* __restrict__ Wenc,
                              const __half* __restrict__ WdecT,
                              float* __restrict__ z_sp,
                              float* __restrict__ xhat,
                              float* __restrict__ act) {
    __shared__ float cv[CAP];
    __shared__ int   ci[CAP];
    __shared__ int   hist[2048];
    __shared__ float xs[DIN];
    __shared__ float sT;
    __shared__ int sureCnt, bandCnt;
    __shared__ int   bidx[BANDCAP];
    __shared__ float bval[BANDCAP];
    __shared__ double sc[BANDCAP];
    __shared__ float sv_s[TOPK];
    __shared__ int   si_s[TOPK];

    const int row = blockIdx.x, t = threadIdx.x;
    const int cnt = g_cand_cnt[row];
    if (t == 0) { sureCnt = 0; bandCnt = 0; }
    __syncthreads();

    if (cnt >= 48 && cnt <= CAP) {
        // ---- fast path: rank-select over candidates ----
        for (int i = t; i < cnt; i += 256) {
            uint2 p = g_cand[(size_t)row * CAP + i];
            cv[i] = __uint_as_float(p.x);
            ci[i] = (int)p.y;
        }
        __syncthreads();

        // exact rank under strict total order (value desc, index asc)
        for (int c = t; c < cnt; c += 256) {
            float v = cv[c]; int ix = ci[c];
            int rank = 0;
            for (int j = 0; j < cnt; j++) {
                float u = cv[j];
                rank += (u > v) || (u == v && ci[j] < ix);
            }
            if (rank == TOPK - 1) sT = v;
        }
        __syncthreads();

        const float T = sT, hi = T + BANDM, lo = T - BANDM;
        for (int c = t; c < cnt; c += 256) {
            float v = cv[c];
            if (v > hi) {
                int s = atomicAdd(&sureCnt, 1);
                sv_s[s] = v;
                si_s[s] = ci[c];
                z_sp[(size_t)row * DHID + ci[c]] = v;
            } else if (v >= lo) {
                int e = atomicAdd(&bandCnt, 1);
                if (e < BANDCAP) { bidx[e] = ci[c]; bval[e] = v; }
            }
        }
    } else {
        // ---- fallback: dense radix-select over the z row ----
        const float* zr = z + (size_t)row * DHID;
        unsigned prefix = 0;
        int curShift = 32;
        int need = TOPK;
        const int SH[4] = {21, 13, 5, 0};
        __shared__ unsigned s_prefix;
        __shared__ int s_need;

#pragma unroll
        for (int l = 0; l < 4; l++) {
            const int shift = SH[l];
            const int nb = 1 << (curShift - shift);
            for (int i = t; i < nb; i += 256) hist[i] = 0;
            __syncthreads();
            for (int i = t; i < DHID; i += 256) {
                unsigned b = __float_as_uint(zr[i]);
                if (curShift >= 32 || (b >> curShift) == prefix)
                    atomicAdd(&hist[(b >> shift) & (nb - 1)], 1);
            }
            __syncthreads();
            if (t == 0) {
                int nd = need, bb;
                for (bb = nb - 1; bb > 0; bb--) {
                    int c = hist[bb];
                    if (c >= nd) break;
                    nd -= c;
                }
                s_prefix = (prefix << (curShift - shift)) | (unsigned)bb;
                s_need = nd;
            }
            __syncthreads();
            prefix = s_prefix;
            need = s_need;
            curShift = shift;
            __syncthreads();
        }

        const float Tf = __uint_as_float(prefix);
        const float hi = Tf + BANDM, lo = Tf - BANDM;
        for (int i = t; i < DHID; i += 256) {
            float v = zr[i];
            if (v > hi) {
                int s = atomicAdd(&sureCnt, 1);
                sv_s[s] = v;
                si_s[s] = i;
                z_sp[(size_t)row * DHID + i] = v;
            } else if (v >= lo) {
                int e = atomicAdd(&bandCnt, 1);
                if (e < BANDCAP) { bidx[e] = i; bval[e] = v; }
            }
        }
    }
    __syncthreads();

    // ---- inline fp64 band refinement ----
    const int sure = sureCnt;
    const int bc   = min(bandCnt, BANDCAP);
    const int need = TOPK - sure;

    if (bc > need) {   // contested: exact fp64 ranking
        // cache x row in smem once
        for (int j = t; j < DIN; j += 256) xs[j] = x[(size_t)row * DIN + j];
        __syncthreads();
        const int wd = t >> 5, lane = t & 31;
        for (int c = wd; c < bc; c += 8) {
            const float* wr = Wenc + (size_t)bidx[c] * DIN;
            double s = 0.0;
            for (int j = lane; j < DIN; j += 32)
                s += (double)xs[j] * (double)wr[j];
#pragma unroll
            for (int o = 16; o; o >>= 1)
                s += __shfl_down_sync(0xffffffffu, s, o);
            if (lane == 0) sc[c] = s;
        }
    }
    __syncthreads();

    if (t == 0) {
        int nsel = 0;
        int sel[BANDCAP];
        if (bc <= need) {
            for (int c = 0; c < bc; c++) sel[nsel++] = c;
        } else {
            bool taken[BANDCAP];
            for (int c = 0; c < bc; c++) taken[c] = false;
            for (int r = 0; r < need; r++) {
                int best = -1;
                for (int c = 0; c < bc; c++) {
                    if (taken[c]) continue;
                    if (best < 0 || sc[c] > sc[best] ||
                        (sc[c] == sc[best] && bidx[c] < bidx[best])) best = c;
                }
                taken[best] = true;
                sel[nsel++] = best;
            }
        }
        for (int a = 0; a < nsel; a++) {
            int c = sel[a];
            sv_s[sure + a] = bval[c];
            si_s[sure + a] = bidx[c];
            z_sp[(size_t)row * DHID + bidx[c]] = bval[c];
        }
        for (int a = sure + nsel; a < TOPK; a++) { sv_s[a] = 0.f; si_s[a] = 0; }
        // sort the 32 by index
        for (int a = 1; a < TOPK; a++) {
            float v = sv_s[a]; int ix = si_s[a];
            int b = a - 1;
            while (b >= 0 && si_s[b] > ix) {
                sv_s[b + 1] = sv_s[b]; si_s[b + 1] = si_s[b]; b--;
            }
            sv_s[b + 1] = v; si_s[b + 1] = ix;
        }
        int pos = 0;
        for (int a = 0; a < TOPK; a++)
            if (sv_s[a] > 0.f) pos++;
        atomicAdd(&g_pos, pos);
    }
    __syncthreads();

    // ---- inline decoder: x_hat[row,:] = sum_k sv * WdecT[si,:] (fp16 w) ----
    const int d = t * 4;
    float x0 = 0.f, x1 = 0.f, x2 = 0.f, x3 = 0.f;
#pragma unroll
    for (int k = 0; k < TOPK; k++) {
        const float v = sv_s[k];
        const uint2 w8 = *(const uint2*)(WdecT + (size_t)si_s[k] * DIN + d);
        const __half2 w01 = *reinterpret_cast<const __half2*>(&w8.x);
        const __half2 w23 = *reinterpret_cast<const __half2*>(&w8.y);
        const float2 f01 = __half22float2(w01);
        const float2 f23 = __half22float2(w23);
        x0 += v * f01.x; x1 += v * f01.y; x2 += v * f23.x; x3 += v * f23.y;
    }
    *(float4*)(xhat + (size_t)row * DIN + d) = make_float4(x0, x1, x2, x3);

    // ---- last block writes `active` ----
    if (t == 0) {
        __threadfence();
        int done = atomicAdd(&g_done, 1);
        if (done == NROWS - 1) {
            int total = atomicAdd(&g_pos, 0);
            *act = (float)total / (float)NROWS;
        }
    }
}

// ---------------- launch ----------------
extern "C" void kernel_launch(void* const* d_in, const int* in_sizes, int n_in,
                              void* d_out, int out_size) {
    const float* x     = (const float*)d_in[0];
    const float* W_enc = (const float*)d_in[1];
    const float* W_dec = (const float*)d_in[2];
    float* out = (float*)d_out;

    float* xhat = out + OFF_XHAT;
    float* z_sp = out + OFF_ZSP;
    float* z    = out + OFF_Z;
    float* act  = out + OFF_ACT;

    __half* WdecT;
    cudaGetSymbolAddress((void**)&WdecT, g_WdecT);
    unsigned char *xh, *wh;
    cudaGetSymbolAddress((void**)&xh, g_xh);
    cudaGetSymbolAddress((void**)&wh, g_wh);

    cudaFuncSetAttribute(mma_gemm_kernel, cudaFuncAttributeMaxDynamicSharedMemorySize, GEMM_SMEM);

    prep_kernel<<<12320, 256>>>(x, W_enc, (uint4*)xh, (uint4*)wh);
    mma_gemm_kernel<<<dim3(DHID / 128, NROWS / 128), 256, GEMM_SMEM>>>(xh, wh, W_dec, WdecT, z, z_sp);
    select_kernel<<<NROWS, 256>>>(z, x, W_enc, WdecT, z_sp, xhat, act);
}

// round 16
// speedup vs baseline: 1.4111x; 1.4111x over previous
#include <cuda_runtime.h>
#include <cuda_bf16.h>
#include <cuda_fp16.h>
#include <cstdint>

// Problem constants
#define NROWS   8192
#define DIN     1024
#define DHID    16384
#define TOPK    32
#define BANDCAP 64
#define CAP     1024          // candidate buffer per row
#define TAU     0.78f         // static candidate threshold (~2.3 sigma)
#define BANDM   1e-3f         // refinement band half-width

// Output layout:
//   x_hat    [8192,1024]   @ 0
//   z_sparse [8192,16384]  @ 8388608
//   z        [8192,16384]  @ 142606336
//   active   scalar        @ 276824064
#define OFF_XHAT   0
#define OFF_ZSP    8388608
#define OFF_Z      142606336
#define OFF_ACT    276824064

// -------- device scratch (no allocations allowed) --------
__device__ __half g_WdecT[(size_t)DHID * DIN];                               // 32 MB fp16
__device__ __align__(256) unsigned char g_xh[(size_t)NROWS * DIN * 2];       // fp16 x
__device__ __align__(256) unsigned char g_wh[(size_t)DHID * DIN * 2];        // fp16 W_enc
__device__ uint2 g_cand[(size_t)NROWS * CAP];                                // 64 MB (valbits, idx)
__device__ int   g_cand_cnt[NROWS];
__device__ int   g_pos;
__device__ int   g_done;

// ---------------- PTX helpers (baseline compute_103 feature set only) -------
__device__ __forceinline__ uint32_t smem_u32(const void* p) {
    uint32_t a;
    asm("{ .reg .u64 t; cvta.to.shared.u64 t, %1; cvt.u32.u64 %0, t; }" : "=r"(a) : "l"(p));
    return a;
}
__device__ __forceinline__ void cp16(uint32_t dst, const void* src) {
    asm volatile("cp.async.cg.shared.global [%0], [%1], 16;" :: "r"(dst), "l"(src));
}
#define CP_COMMIT() asm volatile("cp.async.commit_group;" ::: "memory")
#define CP_WAIT1()  asm volatile("cp.async.wait_group 1;" ::: "memory")

__device__ __forceinline__ void ldm4(uint32_t* d, uint32_t addr) {
    asm volatile("ldmatrix.sync.aligned.m8n8.x4.shared.b16 {%0,%1,%2,%3}, [%4];"
        : "=r"(d[0]), "=r"(d[1]), "=r"(d[2]), "=r"(d[3]) : "r"(addr));
}
__device__ __forceinline__ void mma_f16(float* c, const uint32_t* a, const uint32_t* b) {
    asm volatile("mma.sync.aligned.m16n8k16.row.col.f32.f16.f16.f32 "
        "{%0,%1,%2,%3}, {%4,%5,%6,%7}, {%8,%9}, {%0,%1,%2,%3};"
        : "+f"(c[0]), "+f"(c[1]), "+f"(c[2]), "+f"(c[3])
        : "r"(a[0]), "r"(a[1]), "r"(a[2]), "r"(a[3]), "r"(b[0]), "r"(b[1]));
}

// conflict-free chunk swizzle for 128B rows (8 x 16B chunks)
__device__ __forceinline__ uint32_t swz(int r, int c16) {
    return (uint32_t)(r * 128 + ((c16 ^ (r & 7)) << 4));
}

// ---------------- prep: pack W_enc + pack x + reset --------------------------
// block ranges:
//   [0, 8192)        pack W_enc -> fp16      (2048 elems each)
//   [8192, 12288)    pack x -> fp16          (4096 blocks)
//   [12288, 12320)   reset counters          (32 blocks)
__global__ void prep_kernel(const float* __restrict__ x,
                            const float* __restrict__ Wenc,
                            uint4* __restrict__ xh, uint4* __restrict__ wh) {
    const int b = blockIdx.x, t = threadIdx.x;
    if (b < 12288) {
        const bool isW = (b < 8192);
        const int i = (isW ? b : (b - 8192)) * 256 + t;
        const float4* src = (const float4*)(isW ? Wenc : x);
        uint4* dst = isW ? wh : xh;
        float4 a = src[2 * i], c = src[2 * i + 1];
        __half2 h0 = __floats2half2_rn(a.x, a.y);
        __half2 h1 = __floats2half2_rn(a.z, a.w);
        __half2 h2 = __floats2half2_rn(c.x, c.y);
        __half2 h3 = __floats2half2_rn(c.z, c.w);
        uint4 o;
        o.x = *reinterpret_cast<unsigned*>(&h0);
        o.y = *reinterpret_cast<unsigned*>(&h1);
        o.z = *reinterpret_cast<unsigned*>(&h2);
        o.w = *reinterpret_cast<unsigned*>(&h3);
        dst[i] = o;
    } else {
        const int i = (b - 12288) * 256 + t;
        if (i < NROWS) g_cand_cnt[i] = 0;
        if (i == 0) { g_pos = 0; g_done = 0; }
    }
}

// ---------------- encoder: fp16 HMMA GEMM + relu + z_sp zeros + candidates --
// KTILE=64, 3 stages, occupancy 2 (R14 config — the measured optimum).
// Round head is software-pipelined: first ks slice computes before the next
// stage's cp.async burst is issued, restarting the tensor pipe sooner.
#define KTILE   64
#define STAGES  3
#define TILE_B  16384
#define STAGE_B 32768
#define GEMM_SMEM (STAGES * STAGE_B)

__global__ __launch_bounds__(256, 2)
void mma_gemm_kernel(const unsigned char* __restrict__ Ah,
                     const unsigned char* __restrict__ Bh,
                     const float* __restrict__ Wdec,
                     __half* __restrict__ WdecT,
                     float* __restrict__ z, float* __restrict__ z_sp) {
    extern __shared__ unsigned char smem[];
    const uint32_t sb = smem_u32(smem);
    const int tid = threadIdx.x;
    const int lane = tid & 31, warp = tid >> 5;
    const int wm = warp & 3, wn = warp >> 2;
    const int m0 = blockIdx.y * 128, n0 = blockIdx.x * 128;

    // ---- prologue: transpose 2 W_dec tiles using stage smem as scratch ----
    {
        float (*tile)[33] = reinterpret_cast<float (*)[33]>(smem);
        const int L = blockIdx.y * gridDim.x + blockIdx.x;   // 0..8191
        const int tx = tid & 31, ty = tid >> 5;              // (32, 8)
#pragma unroll
        for (int q = 0; q < 2; q++) {
            const int tt = 2 * L + q;
            const int h0 = (tt & 511) * 32;
            const int d0 = (tt >> 9) * 32;
#pragma unroll
            for (int j = 0; j < 32; j += 8)
                tile[ty + j][tx] = Wdec[(size_t)(d0 + ty + j) * DHID + h0 + tx];
            __syncthreads();
#pragma unroll
            for (int j = 0; j < 32; j += 8)
                WdecT[(size_t)(h0 + ty + j) * DIN + d0 + tx] = __float2half(tile[tx][ty + j]);
            __syncthreads();
        }
    }

    float acc[2][8][4];
#pragma unroll
    for (int i = 0; i < 2; i++)
#pragma unroll
        for (int j = 0; j < 8; j++)
#pragma unroll
            for (int q = 0; q < 4; q++) acc[i][j][q] = 0.f;

    // stage loader: 2 subtiles x 1024 16B-chunks, 8 cp.async per thread
    auto load_stage = [&](int s, int kc) {
        const uint32_t stage = sb + s * STAGE_B;
#pragma unroll
        for (int t = 0; t < 2; t++) {
            const int r0 = t ? n0 : m0;
            const unsigned char* g = t ? Bh : Ah;
#pragma unroll
            for (int rep = 0; rep < 4; rep++) {
                const int j = tid + rep * 256;
                const int r = j >> 3, c16 = j & 7;
                const unsigned char* src = g + (((size_t)(r0 + r) << 10) + kc * 64 + c16 * 8) * 2;
                cp16(stage + t * TILE_B + swz(r, c16), src);
            }
        }
    };

    // one ks slice (16 K-values) of the current stage
    auto do_ks = [&](uint32_t stage, int ks) {
        uint32_t ah[2][4], bh[8][2];
#pragma unroll
        for (int i = 0; i < 2; i++) {
            const int row = wm * 32 + i * 16 + (lane & 15);
            const int c16 = ks * 2 + (lane >> 4);
            ldm4(ah[i], stage + swz(row, c16));
        }
#pragma unroll
        for (int g = 0; g < 4; g++) {
            const int row = wn * 64 + g * 16 + (lane & 7) + ((lane >> 4) << 3);
            const int c16 = ks * 2 + ((lane >> 3) & 1);
            uint32_t d[4];
            ldm4(d, stage + TILE_B + swz(row, c16));
            bh[2 * g][0] = d[0]; bh[2 * g][1] = d[1];
            bh[2 * g + 1][0] = d[2]; bh[2 * g + 1][1] = d[3];
        }
#pragma unroll
        for (int i = 0; i < 2; i++)
#pragma unroll
            for (int j = 0; j < 8; j++)
                mma_f16(acc[i][j], ah[i], bh[j]);
    };

    load_stage(0, 0); CP_COMMIT();
    load_stage(1, 1); CP_COMMIT();

    for (int kc = 0; kc < DIN / KTILE; kc++) {      // 16 iterations
        CP_WAIT1();                      // stage kc's data complete
        __syncthreads();                 // all threads done reading stage kc-1
        const uint32_t stage = sb + (kc % STAGES) * STAGE_B;
        do_ks(stage, 0);                 // restart tensor pipe first
        if (kc + 2 < DIN / KTILE) load_stage((kc + 2) % STAGES, kc + 2);
        CP_COMMIT();
#pragma unroll
        for (int ks = 1; ks < 4; ks++)
            do_ks(stage, ks);
    }

    // epilogue: relu + z store + z_sp zero store + candidate push (v > TAU)
    const int mbase = m0 + wm * 32, nbase = n0 + wn * 64;
    const float2 zero2 = make_float2(0.f, 0.f);
#pragma unroll
    for (int i = 0; i < 2; i++)
#pragma unroll
        for (int j = 0; j < 8; j++) {
            const int r = mbase + i * 16 + (lane >> 2);
            const int c = nbase + j * 8 + (lane & 3) * 2;
            float2 v0, v1;
            v0.x = fmaxf(acc[i][j][0], 0.f); v0.y = fmaxf(acc[i][j][1], 0.f);
            v1.x = fmaxf(acc[i][j][2], 0.f); v1.y = fmaxf(acc[i][j][3], 0.f);
            *(float2*)(z + (size_t)r * DHID + c) = v0;
            *(float2*)(z + (size_t)(r + 8) * DHID + c) = v1;
            *(float2*)(z_sp + (size_t)r * DHID + c) = zero2;
            *(float2*)(z_sp + (size_t)(r + 8) * DHID + c) = zero2;
            if (v0.x > TAU) { int s = atomicAdd(&g_cand_cnt[r], 1);
                if (s < CAP) g_cand[(size_t)r * CAP + s] = make_uint2(__float_as_uint(v0.x), c); }
            if (v0.y > TAU) { int s = atomicAdd(&g_cand_cnt[r], 1);
                if (s < CAP) g_cand[(size_t)r * CAP + s] = make_uint2(__float_as_uint(v0.y), c + 1); }
            if (v1.x > TAU) { int s = atomicAdd(&g_cand_cnt[r + 8], 1);
                if (s < CAP) g_cand[(size_t)(r + 8) * CAP + s] = make_uint2(__float_as_uint(v1.x), c); }
            if (v1.y > TAU) { int s = atomicAdd(&g_cand_cnt[r + 8], 1);
                if (s < CAP) g_cand[(size_t)(r + 8) * CAP + s] = make_uint2(__float_as_uint(v1.y), c + 1); }
        }
}

// ---------------- merged: top-k + fallback + fp64 refine + decoder + active -
// One block (256 threads) per row; the last block to finish writes `active`.
__global__ void select_kernel(const float* __restrict__ z,
                              const float* __restrict__ x,
                              const float* __restrict__ Wenc,
                              const __half* __restrict__ WdecT,
                              float* __restrict__ z_sp,
                              float* __restrict__ xhat,
                              float* __restrict__ act) {
    __shared__ float cv[CAP];
    __shared__ int   ci[CAP];
    __shared__ int   hist[2048];
    __shared__ float xs[DIN];
    __shared__ float sT;
    __shared__ int sureCnt, bandCnt;
    __shared__ int   bidx[BANDCAP];
    __shared__ float bval[BANDCAP];
    __shared__ double sc[BANDCAP];
    __shared__ float sv_s[TOPK];
    __shared__ int   si_s[TOPK];

    const int row = blockIdx.x, t = threadIdx.x;
    const int cnt = g_cand_cnt[row];
    if (t == 0) { sureCnt = 0; bandCnt = 0; }
    __syncthreads();

    if (cnt >= 48 && cnt <= CAP) {
        // ---- fast path: rank-select over candidates ----
        for (int i = t; i < cnt; i += 256) {
            uint2 p = g_cand[(size_t)row * CAP + i];
            cv[i] = __uint_as_float(p.x);
            ci[i] = (int)p.y;
        }
        __syncthreads();

        // exact rank under strict total order (value desc, index asc)
        for (int c = t; c < cnt; c += 256) {
            float v = cv[c]; int ix = ci[c];
            int rank = 0;
            for (int j = 0; j < cnt; j++) {
                float u = cv[j];
                rank += (u > v) || (u == v && ci[j] < ix);
            }
            if (rank == TOPK - 1) sT = v;
        }
        __syncthreads();

        const float T = sT, hi = T + BANDM, lo = T - BANDM;
        for (int c = t; c < cnt; c += 256) {
            float v = cv[c];
            if (v > hi) {
                int s = atomicAdd(&sureCnt, 1);
                sv_s[s] = v;
                si_s[s] = ci[c];
                z_sp[(size_t)row * DHID + ci[c]] = v;
            } else if (v >= lo) {
                int e = atomicAdd(&bandCnt, 1);
                if (e < BANDCAP) { bidx[e] = ci[c]; bval[e] = v; }
            }
        }
    } else {
        // ---- fallback: dense radix-select over the z row ----
        const float* zr = z + (size_t)row * DHID;
        unsigned prefix = 0;
        int curShift = 32;
        int need = TOPK;
        const int SH[4] = {21, 13, 5, 0};
        __shared__ unsigned s_prefix;
        __shared__ int s_need;

#pragma unroll
        for (int l = 0; l < 4; l++) {
            const int shift = SH[l];
            const int nb = 1 << (curShift - shift);
            for (int i = t; i < nb; i += 256) hist[i] = 0;
            __syncthreads();
            for (int i = t; i < DHID; i += 256) {
                unsigned b = __float_as_uint(zr[i]);
                if (curShift >= 32 || (b >> curShift) == prefix)
                    atomicAdd(&hist[(b >> shift) & (nb - 1)], 1);
            }
            __syncthreads();
            if (t == 0) {
                int nd = need, bb;
                for (bb = nb - 1; bb > 0; bb--) {
                    int c = hist[bb];
                    if (c >= nd) break;
                    nd -= c;
                }
                s_prefix = (prefix << (curShift - shift)) | (unsigned)bb;
                s_need = nd;
            }
            __syncthreads();
            prefix = s_prefix;
            need = s_need;
            curShift = shift;
            __syncthreads();
        }

        const float Tf = __uint_as_float(prefix);
        const float hi = Tf + BANDM, lo = Tf - BANDM;
        for (int i = t; i < DHID; i += 256) {
            float v = zr[i];
            if (v > hi) {
                int s = atomicAdd(&sureCnt, 1);
                sv_s[s] = v;
                si_s[s] = i;
                z_sp[(size_t)row * DHID + i] = v;
            } else if (v >= lo) {
                int e = atomicAdd(&bandCnt, 1);
                if (e < BANDCAP) { bidx[e] = i; bval[e] = v; }
            }
        }
    }
    __syncthreads();

    // ---- inline fp64 band refinement ----
    const int sure = sureCnt;
    const int bc   = min(bandCnt, BANDCAP);
    const int need = TOPK - sure;

    if (bc > need) {   // contested: exact fp64 ranking
        // cache x row in smem once
        for (int j = t; j < DIN; j += 256) xs[j] = x[(size_t)row * DIN + j];
        __syncthreads();
        const int wd = t >> 5, lane = t & 31;
        for (int c = wd; c < bc; c += 8) {
            const float* wr = Wenc + (size_t)bidx[c] * DIN;
            double s = 0.0;
            for (int j = lane; j < DIN; j += 32)
                s += (double)xs[j] * (double)wr[j];
#pragma unroll
            for (int o = 16; o; o >>= 1)
                s += __shfl_down_sync(0xffffffffu, s, o);
            if (lane == 0) sc[c] = s;
        }
    }
    __syncthreads();

    if (t == 0) {
        int nsel = 0;
        int sel[BANDCAP];
        if (bc <= need) {
            for (int c = 0; c < bc; c++) sel[nsel++] = c;
        } else {
            bool taken[BANDCAP];
            for (int c = 0; c < bc; c++) taken[c] = false;
            for (int r = 0; r < need; r++) {
                int best = -1;
                for (int c = 0; c < bc; c++) {
                    if (taken[c]) continue;
                    if (best < 0 || sc[c] > sc[best] ||
                        (sc[c] == sc[best] && bidx[c] < bidx[best])) best = c;
                }
                taken[best] = true;
                sel[nsel++] = best;
            }
        }
        for (int a = 0; a < nsel; a++) {
            int c = sel[a];
            sv_s[sure + a] = bval[c];
            si_s[sure + a] = bidx[c];
            z_sp[(size_t)row * DHID + bidx[c]] = bval[c];
        }
        for (int a = sure + nsel; a < TOPK; a++) { sv_s[a] = 0.f; si_s[a] = 0; }
        // sort the 32 by index
        for (int a = 1; a < TOPK; a++) {
            float v = sv_s[a]; int ix = si_s[a];
            int b = a - 1;
            while (b >= 0 && si_s[b] > ix) {
                sv_s[b + 1] = sv_s[b]; si_s[b + 1] = si_s[b]; b--;
            }
            sv_s[b + 1] = v; si_s[b + 1] = ix;
        }
        int pos = 0;
        for (int a = 0; a < TOPK; a++)
            if (sv_s[a] > 0.f) pos++;
        atomicAdd(&g_pos, pos);
    }
    __syncthreads();

    // ---- inline decoder: x_hat[row,:] = sum_k sv * WdecT[si,:] (fp16 w) ----
    const int d = t * 4;
    float x0 = 0.f, x1 = 0.f, x2 = 0.f, x3 = 0.f;
#pragma unroll
    for (int k = 0; k < TOPK; k++) {
        const float v = sv_s[k];
        const uint2 w8 = *(const uint2*)(WdecT + (size_t)si_s[k] * DIN + d);
        const __half2 w01 = *reinterpret_cast<const __half2*>(&w8.x);
        const __half2 w23 = *reinterpret_cast<const __half2*>(&w8.y);
        const float2 f01 = __half22float2(w01);
        const float2 f23 = __half22float2(w23);
        x0 += v * f01.x; x1 += v * f01.y; x2 += v * f23.x; x3 += v * f23.y;
    }
    *(float4*)(xhat + (size_t)row * DIN + d) = make_float4(x0, x1, x2, x3);

    // ---- last block writes `active` ----
    if (t == 0) {
        __threadfence();
        int done = atomicAdd(&g_done, 1);
        if (done == NROWS - 1) {
            int total = atomicAdd(&g_pos, 0);
            *act = (float)total / (float)NROWS;
        }
    }
}

// ---------------- launch ----------------
extern "C" void kernel_launch(void* const* d_in, const int* in_sizes, int n_in,
                              void* d_out, int out_size) {
    const float* x     = (const float*)d_in[0];
    const float* W_enc = (const float*)d_in[1];
    const float* W_dec = (const float*)d_in[2];
    float* out = (float*)d_out;

    float* xhat = out + OFF_XHAT;
    float* z_sp = out + OFF_ZSP;
    float* z    = out + OFF_Z;
    float* act  = out + OFF_ACT;

    __half* WdecT;
    cudaGetSymbolAddress((void**)&WdecT, g_WdecT);
    unsigned char *xh, *wh;
    cudaGetSymbolAddress((void**)&xh, g_xh);
    cudaGetSymbolAddress((void**)&wh, g_wh);

    cudaFuncSetAttribute(mma_gemm_kernel, cudaFuncAttributeMaxDynamicSharedMemorySize, GEMM_SMEM);

    prep_kernel<<<12320, 256>>>(x, W_enc, (uint4*)xh, (uint4*)wh);
    mma_gemm_kernel<<<dim3(DHID / 128, NROWS / 128), 256, GEMM_SMEM>>>(xh, wh, W_dec, WdecT, z, z_sp);
    select_kernel<<<NROWS, 256>>>(z, x, W_enc, WdecT, z_sp, xhat, act);
}